// round 9
// baseline (speedup 1.0000x reference)
#include <cuda_runtime.h>
#include <math.h>

#define KU 128      // users (K)
#define MD 1024     // M
#define NU 128      // N (== KU)
#define KT 8        // k rows per block tile
#define MCH 16      // m rows per block chunk
#define NKT (KU / KT)    // 16
#define NMC (MD / MCH)   // 64
static __device__ __constant__ float N0F = 1e-11f;  // 10^(-80/10)/1000

// Scratch (static __device__ — no allocation)
__device__ float d_gp_re[NMC * KU * NU];   // per-m-chunk partials of g (4 MB)
__device__ float d_gp_im[NMC * KU * NU];
__device__ float d_R[KU];
__device__ unsigned int d_ktctr[NKT];      // per-kt completion counters
__device__ unsigned int d_ctr;             // kt-finisher counter

__device__ __forceinline__ float dot4(float4 a, float4 b) {
    return fmaf(a.x, b.x, fmaf(a.y, b.y, fmaf(a.z, b.z, a.w * b.w)));
}

// ---------------------------------------------------------------------------
// Single fused kernel.
//   stage A: h = h_d + A v for an (8k x 16m) tile (DRAM stream, 128 KB/block)
//   stage B: contract tile against W[m0:m0+16,:] (L2) -> g partials
//   epilogue: last block per kt reduces partials -> mag -> rowsum -> R[k];
//             last kt-finisher does the global sum and writes out.
// grid (64 mc, 16 kt) = 1024 blocks x 256 threads; launch_bounds(,6) caps
// regs so 6 blocks (48 warps, 75% occ) are resident per SM.
// ---------------------------------------------------------------------------
__global__ __launch_bounds__(256, 6) void k12_fused(
    const float* __restrict__ Wv,
    const float* __restrict__ Ar,
    const float* __restrict__ Ai,
    const float* __restrict__ hdr,
    const float* __restrict__ hdi,
    float* __restrict__ out)
{
    __shared__ float hsrt[MCH * 8];   // h_re transposed [m][kk]
    __shared__ float hsit[MCH * 8];   // h_im transposed [m][kk]
    __shared__ float mg[KT][NU];      // epilogue magnitudes
    __shared__ float red[128];
    __shared__ unsigned int flag_s;

    const int tid  = threadIdx.x;
    const int lane = tid & 31;
    const int warp = tid >> 5;        // 0..7 == kk
    const int c    = lane & 15;       // position within 16-lane half
    const int sub  = lane >> 4;       // which row of the pair

    const int mc = blockIdx.x;        // 0..63
    const int kt = blockIdx.y;        // 0..15
    const int k0 = kt * KT;
    const int m0 = mc * MCH;

    // v_re / v_im (2 float4 per half-lane)
    const float4* vr4 = reinterpret_cast<const float4*>(Wv);
    const float4* vi4 = reinterpret_cast<const float4*>(Wv + 128);
    const float4 v0r = vr4[c], v1r = vr4[c + 16];
    const float4 v0i = vi4[c], v1i = vi4[c + 16];

    // ---- stage A: warp `warp` owns kk = warp, all 16 m's (8 KB contiguous) ----
    const int kk = warp;
    const size_t rbase = (size_t)(k0 + kk) * MD + m0;
#pragma unroll 4
    for (int it = 0; it < 8; it++) {
        const int m   = it * 2 + sub;
        const size_t row = rbase + m;
        const float4* ar = reinterpret_cast<const float4*>(Ar + row * NU);
        const float4* ai = reinterpret_cast<const float4*>(Ai + row * NU);
        const float4 a0 = ar[c], a1 = ar[c + 16];
        const float4 b0 = ai[c], b1 = ai[c + 16];

        float sre = dot4(a0, v0r) + dot4(a1, v1r) - dot4(b0, v0i) - dot4(b1, v1i);
        float sim = dot4(b0, v0r) + dot4(b1, v1r) + dot4(a0, v0i) + dot4(a1, v1i);

#pragma unroll
        for (int off = 8; off; off >>= 1) {
            sre += __shfl_xor_sync(0xffffffffu, sre, off);
            sim += __shfl_xor_sync(0xffffffffu, sim, off);
        }
        if (c == 0) {
            hsrt[m * 8 + kk] = hdr[row] + sre;
            hsit[m * 8 + kk] = hdi[row] + sim;
        }
    }
    __syncthreads();

    // ---- stage B: g_partial[kk, n] += sum_m h[kk,m] * W[m0+m, n] (complex) ----
    const int n = tid & 127;          // output column
    const int g = tid >> 7;           // kk group: g*4 .. g*4+3
    {
        float are[4] = {0.f, 0.f, 0.f, 0.f};
        float aim[4] = {0.f, 0.f, 0.f, 0.f};
        const float* Wb = Wv + (size_t)(1 + m0) * 256;   // W rows m0.., stride 256

#pragma unroll 4
        for (int m = 0; m < MCH; m++) {
            const float wre = __ldg(Wb + m * 256 + n);
            const float wim = __ldg(Wb + m * 256 + 128 + n);
            const float4 hre = *reinterpret_cast<const float4*>(&hsrt[m * 8 + g * 4]);
            const float4 him = *reinterpret_cast<const float4*>(&hsit[m * 8 + g * 4]);

            are[0] = fmaf(hre.x, wre, fmaf(-him.x, wim, are[0]));
            aim[0] = fmaf(hre.x, wim, fmaf( him.x, wre, aim[0]));
            are[1] = fmaf(hre.y, wre, fmaf(-him.y, wim, are[1]));
            aim[1] = fmaf(hre.y, wim, fmaf( him.y, wre, aim[1]));
            are[2] = fmaf(hre.z, wre, fmaf(-him.z, wim, are[2]));
            aim[2] = fmaf(hre.z, wim, fmaf( him.z, wre, aim[2]));
            are[3] = fmaf(hre.w, wre, fmaf(-him.w, wim, are[3]));
            aim[3] = fmaf(hre.w, wim, fmaf( him.w, wre, aim[3]));
        }

#pragma unroll
        for (int j = 0; j < 4; j++) {
            const int kidx = k0 + g * 4 + j;
            d_gp_re[mc * (KU * NU) + kidx * NU + n] = are[j];
            d_gp_im[mc * (KU * NU) + kidx * NU + n] = aim[j];
        }
    }

    // ---- epilogue arbitration: last block of this kt reduces it ----
    if (tid == 0) {
        __threadfence();
        flag_s = (atomicAdd(&d_ktctr[kt], 1u) == NMC - 1) ? 1u : 0u;
    }
    __syncthreads();
    if (!flag_s) return;
    __threadfence();   // acquire: other blocks' partials now visible

    // ---- reduce 64 partials for 8 k-rows; mag into smem ----
    // thread (n, g) handles k = g*4 + j, j = 0..3
#pragma unroll
    for (int j = 0; j < 4; j++) {
        const int kq = g * 4 + j;
        const int kg = k0 + kq;
        float gre = 0.f, gim = 0.f;
#pragma unroll 8
        for (int p = 0; p < NMC; p++) {
            gre += d_gp_re[p * (KU * NU) + kg * NU + n];
            gim += d_gp_im[p * (KU * NU) + kg * NU + n];
        }
        mg[kq][n] = sqrtf(gre * gre + gim * gim);
    }
    __syncthreads();

    // ---- per-k rowsum + R[k]: warp w handles k-row w ----
    {
        const int w = warp;           // 0..7
        float s = mg[w][lane] + mg[w][lane + 32] + mg[w][lane + 64] + mg[w][lane + 96];
#pragma unroll
        for (int off = 16; off; off >>= 1)
            s += __shfl_xor_sync(0xffffffffu, s, off);
        if (lane == 0) {
            const float sig = mg[w][k0 + w];   // diagonal: n == global k index
            d_R[k0 + w] = sig / (s - sig + N0F);
        }
    }
    __syncthreads();

    // ---- final sum: last kt-finisher ----
    if (tid == 0) {
        __threadfence();
        flag_s = (atomicAdd(&d_ctr, 1u) == NKT - 1) ? 1u : 0u;
    }
    __syncthreads();
    if (!flag_s) return;
    __threadfence();

    if (tid < 128) red[tid] = d_R[tid];
    __syncthreads();
#pragma unroll
    for (int s = 64; s > 0; s >>= 1) {
        if (tid < s) red[tid] += red[tid + s];
        __syncthreads();
    }
    if (tid == 0) {
        out[0] = -red[0] * 1e6f;
        // reset counters for next graph replay
        d_ctr = 0;
#pragma unroll
        for (int i = 0; i < NKT; i++) d_ktctr[i] = 0;
    }
}

// ---------------------------------------------------------------------------
extern "C" void kernel_launch(void* const* d_in, const int* in_sizes, int n_in,
                              void* d_out, int out_size)
{
    const float* Wv  = (const float*)d_in[0];  // (1025, 256)
    const float* Ar  = (const float*)d_in[1];  // (128, 1024, 128)
    const float* Ai  = (const float*)d_in[2];
    const float* hdr = (const float*)d_in[3];  // (128, 1024)
    const float* hdi = (const float*)d_in[4];

    k12_fused<<<dim3(NMC, NKT), 256>>>(Wv, Ar, Ai, hdr, hdi, (float*)d_out);
}

// round 10
// speedup vs baseline: 1.4125x; 1.4125x over previous
#include <cuda_runtime.h>
#include <math.h>
#include <stdint.h>

#define KU 128      // users (K)
#define MD 1024     // M
#define NU 128      // N (== KU)
#define KT 8        // k rows per block tile
#define MCH 32      // m rows per block chunk
#define NKT (KU / KT)    // 16
#define NMC (MD / MCH)   // 32
#define NCH (MCH / 2)    // 16 chunks of 2 m-rows
#define STAGES 3
static __device__ __constant__ float N0F = 1e-11f;  // 10^(-80/10)/1000

// Scratch (static __device__ — no allocation)
__device__ float d_gp_re[NMC * KU * NU];   // per-m-chunk partials of g (2 MB)
__device__ float d_gp_im[NMC * KU * NU];
__device__ float d_R[KU];
__device__ unsigned int d_ctr;             // last-block counter for k3

__device__ __forceinline__ float dot4(float4 a, float4 b) {
    return fmaf(a.x, b.x, fmaf(a.y, b.y, fmaf(a.z, b.z, a.w * b.w)));
}

__device__ __forceinline__ void cp16(uint32_t dst, const void* src) {
    asm volatile("cp.async.cg.shared.global [%0], [%1], 16;\n" :: "r"(dst), "l"(src));
}
__device__ __forceinline__ void cp_commit() {
    asm volatile("cp.async.commit_group;\n" ::: "memory");
}
__device__ __forceinline__ void cp_wait2() {
    asm volatile("cp.async.wait_group 2;\n" ::: "memory");
}

// ---------------------------------------------------------------------------
// k12: stage A streams A via a warp-local 3-deep cp.async ring (loads never
// blocked by the shfl reduce chains), stage B contracts h against W (L2).
// grid (32 mc, 16 kt) = 512 blocks x 256 threads, dynamic smem 51.2 KB.
// Ring layout per warp (floats): slot s (512 f): [Ar row0 |Ar row1 |Ai row0 |Ai row1]
// ---------------------------------------------------------------------------
extern __shared__ float dynsm[];
__global__ __launch_bounds__(256, 4) void k12_fused(
    const float* __restrict__ Wv,
    const float* __restrict__ Ar,
    const float* __restrict__ Ai,
    const float* __restrict__ hdr,
    const float* __restrict__ hdi)
{
    float* ring  = dynsm;                 // 8 warps * 3 slots * 512 floats = 12288
    float* hsrt  = dynsm + 12288;         // [m][kk] 256 floats
    float* hsit  = hsrt + 256;

    const int tid  = threadIdx.x;
    const int lane = tid & 31;
    const int warp = tid >> 5;            // 0..7 == kk
    const int c    = lane & 15;
    const int sub  = lane >> 4;

    const int mc = blockIdx.x;            // 0..31
    const int kt = blockIdx.y;            // 0..15
    const int k0 = kt * KT;
    const int m0 = mc * MCH;

    const float4* vr4 = reinterpret_cast<const float4*>(Wv);
    const float4* vi4 = reinterpret_cast<const float4*>(Wv + 128);
    const float4 v0r = vr4[c], v1r = vr4[c + 16];
    const float4 v0i = vi4[c], v1i = vi4[c + 16];

    const int kk = warp;
    const float* arow = Ar + ((size_t)(k0 + kk) * MD + m0) * NU;
    const float* brow = Ai + ((size_t)(k0 + kk) * MD + m0) * NU;

    float* wring = ring + warp * (STAGES * 512);
    const uint32_t wbase = (uint32_t)__cvta_generic_to_shared(wring);

    // ---- prologue: issue chunks 0..2 ----
#pragma unroll
    for (int s = 0; s < STAGES; s++) {
        const uint32_t sb = wbase + (uint32_t)s * 2048u + (uint32_t)lane * 16u;
        cp16(sb,         arow + (s * 2 + 0) * NU + lane * 4);
        cp16(sb + 512u,  arow + (s * 2 + 1) * NU + lane * 4);
        cp16(sb + 1024u, brow + (s * 2 + 0) * NU + lane * 4);
        cp16(sb + 1536u, brow + (s * 2 + 1) * NU + lane * 4);
        cp_commit();
    }

    // ---- stage A main loop: 16 chunks of 2 m-rows ----
    int slot = 0;
    for (int it = 0; it < NCH; ++it) {
        cp_wait2();                 // chunk `it` complete (3 groups outstanding)
        __syncwarp();

        const float* sp = wring + slot * 512;
        const float4* pa = reinterpret_cast<const float4*>(sp + sub * 128);
        const float4* pb = reinterpret_cast<const float4*>(sp + 256 + sub * 128);
        const float4 a0 = pa[c], a1 = pa[c + 16];
        const float4 b0 = pb[c], b1 = pb[c + 16];

        // refill this slot with chunk it+STAGES (empty group at tail keeps count)
        const int jn = it + STAGES;
        if (jn < NCH) {
            const uint32_t sb = wbase + (uint32_t)slot * 2048u + (uint32_t)lane * 16u;
            cp16(sb,         arow + (jn * 2 + 0) * NU + lane * 4);
            cp16(sb + 512u,  arow + (jn * 2 + 1) * NU + lane * 4);
            cp16(sb + 1024u, brow + (jn * 2 + 0) * NU + lane * 4);
            cp16(sb + 1536u, brow + (jn * 2 + 1) * NU + lane * 4);
        }
        cp_commit();

        float sre = dot4(a0, v0r) + dot4(a1, v1r) - dot4(b0, v0i) - dot4(b1, v1i);
        float sim = dot4(b0, v0r) + dot4(b1, v1r) + dot4(a0, v0i) + dot4(a1, v1i);
#pragma unroll
        for (int off = 8; off; off >>= 1) {
            sre += __shfl_xor_sync(0xffffffffu, sre, off);
            sim += __shfl_xor_sync(0xffffffffu, sim, off);
        }
        const int m = it * 2 + sub;
        if (c == 0) {
            const size_t row = (size_t)(k0 + kk) * MD + m0 + m;
            hsrt[m * 8 + kk] = hdr[row] + sre;
            hsit[m * 8 + kk] = hdi[row] + sim;
        }
        slot = (slot == STAGES - 1) ? 0 : slot + 1;
    }
    __syncthreads();

    // ---- stage B: g_partial[kk, n] += sum_m h[kk,m] * W[m0+m, n] (complex) ----
    const int n = tid & 127;
    const int g = tid >> 7;               // kk group: g*4 .. g*4+3
    float are[4] = {0.f, 0.f, 0.f, 0.f};
    float aim[4] = {0.f, 0.f, 0.f, 0.f};
    const float* Wb = Wv + (size_t)(1 + m0) * 256;

#pragma unroll 4
    for (int m = 0; m < MCH; m++) {
        const float wre = __ldg(Wb + m * 256 + n);
        const float wim = __ldg(Wb + m * 256 + 128 + n);
        const float4 hre = *reinterpret_cast<const float4*>(&hsrt[m * 8 + g * 4]);
        const float4 him = *reinterpret_cast<const float4*>(&hsit[m * 8 + g * 4]);

        are[0] = fmaf(hre.x, wre, fmaf(-him.x, wim, are[0]));
        aim[0] = fmaf(hre.x, wim, fmaf( him.x, wre, aim[0]));
        are[1] = fmaf(hre.y, wre, fmaf(-him.y, wim, are[1]));
        aim[1] = fmaf(hre.y, wim, fmaf( him.y, wre, aim[1]));
        are[2] = fmaf(hre.z, wre, fmaf(-him.z, wim, are[2]));
        aim[2] = fmaf(hre.z, wim, fmaf( him.z, wre, aim[2]));
        are[3] = fmaf(hre.w, wre, fmaf(-him.w, wim, are[3]));
        aim[3] = fmaf(hre.w, wim, fmaf( him.w, wre, aim[3]));
    }

#pragma unroll
    for (int j = 0; j < 4; j++) {
        const int kidx = k0 + g * 4 + j;
        d_gp_re[mc * (KU * NU) + kidx * NU + n] = are[j];
        d_gp_im[mc * (KU * NU) + kidx * NU + n] = aim[j];
    }
}

// ---------------------------------------------------------------------------
// k3: per-k reduce partials -> mag -> rowsum -> R[k]; last block sums R and
// writes out. grid 128 x 1024 threads: thread = (n, pg of 8) -> 4 loads each.
// ---------------------------------------------------------------------------
__global__ __launch_bounds__(1024) void k3_rate(float* __restrict__ out)
{
    const int k   = blockIdx.x;
    const int tid = threadIdx.x;
    const int n   = tid & 127;
    const int pg  = tid >> 7;   // 0..7

    float gre = 0.f, gim = 0.f;
#pragma unroll
    for (int p = pg; p < NMC; p += 8) {   // 4 partials per thread
        gre += d_gp_re[p * (KU * NU) + k * NU + n];
        gim += d_gp_im[p * (KU * NU) + k * NU + n];
    }

    __shared__ float sre[1024];
    __shared__ float sim[1024];
    __shared__ float red[128];
    __shared__ float sig_s;
    __shared__ unsigned int last_s;
    sre[tid] = gre;
    sim[tid] = gim;
    __syncthreads();

    if (pg == 0) {
        gre = ((sre[n]       + sre[n + 128]) + (sre[n + 256] + sre[n + 384]))
            + ((sre[n + 512] + sre[n + 640]) + (sre[n + 768] + sre[n + 896]));
        gim = ((sim[n]       + sim[n + 128]) + (sim[n + 256] + sim[n + 384]))
            + ((sim[n + 512] + sim[n + 640]) + (sim[n + 768] + sim[n + 896]));
        const float mag = sqrtf(gre * gre + gim * gim);
        red[n] = mag;
        if (n == k) sig_s = mag;
    }
    __syncthreads();
#pragma unroll
    for (int s = 64; s > 0; s >>= 1) {
        if (tid < s) red[tid] += red[tid + s];
        __syncthreads();
    }
    if (tid == 0) {
        const float sig = sig_s;
        d_R[k] = sig / (red[0] - sig + N0F);
        __threadfence();
        last_s = atomicAdd(&d_ctr, 1u);
    }
    __syncthreads();

    if (last_s == KU - 1) {
        __threadfence();
        if (tid < 128) red[tid] = d_R[tid];
        __syncthreads();
#pragma unroll
        for (int s = 64; s > 0; s >>= 1) {
            if (tid < s) red[tid] += red[tid + s];
            __syncthreads();
        }
        if (tid == 0) {
            out[0] = -red[0] * 1e6f;
            d_ctr = 0;   // reset for next graph replay
        }
    }
}

// ---------------------------------------------------------------------------
extern "C" void kernel_launch(void* const* d_in, const int* in_sizes, int n_in,
                              void* d_out, int out_size)
{
    const float* Wv  = (const float*)d_in[0];  // (1025, 256)
    const float* Ar  = (const float*)d_in[1];  // (128, 1024, 128)
    const float* Ai  = (const float*)d_in[2];
    const float* hdr = (const float*)d_in[3];  // (128, 1024)
    const float* hdi = (const float*)d_in[4];

    const int dynBytes = (12288 + 512) * 4;    // ring 48K + h tile 2K = 51200 B
    cudaFuncSetAttribute(k12_fused, cudaFuncAttributeMaxDynamicSharedMemorySize,
                         dynBytes);

    k12_fused<<<dim3(NMC, NKT), 256, dynBytes>>>(Wv, Ar, Ai, hdr, hdi);
    k3_rate<<<KU, 1024>>>((float*)d_out);
}